// round 15
// baseline (speedup 1.0000x reference)
#include <cuda_runtime.h>
#include <cuda_fp16.h>
#include <cstdint>

// Problem constants
#define B_TOT   2048
#define NSEQ    49
#define CDIM    256
#define NHEADS  8
#define DHEAD   32
#define NW      64
#define THREECD 768

// Scratch (allocation-free rule: __device__ globals)
__device__ __align__(16) __half g_xh[(size_t)B_TOT * NSEQ * CDIM];       // x fp16
__device__ __align__(16) __half g_wqkvh[(size_t)CDIM * THREECD];         // qkv_w fp16
__device__ __align__(16) __half g_wprojh[(size_t)CDIM * CDIM];           // proj_w fp16
__device__ __align__(16) __half g_qkvh[(size_t)B_TOT * NSEQ * THREECD];  // qkv fp16
__device__ __align__(16) __half g_aoh[(size_t)B_TOT * NSEQ * CDIM];      // attn out fp16
__device__ float g_comb[(size_t)NW * NHEADS * NSEQ * NSEQ];              // bias+mask

// ---------------------------------------------------------------------------
// PTX helpers (legacy mma path — tcgen05 unavailable on sm_103 PTX target)
// ---------------------------------------------------------------------------
__device__ __forceinline__ void mma_f16(float (&c)[4], const unsigned (&a)[4],
                                        unsigned b0, unsigned b1) {
    asm volatile(
        "mma.sync.aligned.m16n8k16.row.col.f32.f16.f16.f32 "
        "{%0,%1,%2,%3}, {%4,%5,%6,%7}, {%8,%9}, {%0,%1,%2,%3};\n"
        : "+f"(c[0]), "+f"(c[1]), "+f"(c[2]), "+f"(c[3])
        : "r"(a[0]), "r"(a[1]), "r"(a[2]), "r"(a[3]), "r"(b0), "r"(b1));
}
__device__ __forceinline__ void ldsm4(unsigned (&r)[4], unsigned addr) {
    asm volatile("ldmatrix.sync.aligned.m8n8.x4.shared.b16 {%0,%1,%2,%3}, [%4];"
        : "=r"(r[0]), "=r"(r[1]), "=r"(r[2]), "=r"(r[3]) : "r"(addr));
}
__device__ __forceinline__ void ldsm4t(unsigned (&r)[4], unsigned addr) {
    asm volatile("ldmatrix.sync.aligned.m8n8.x4.trans.shared.b16 {%0,%1,%2,%3}, [%4];"
        : "=r"(r[0]), "=r"(r[1]), "=r"(r[2]), "=r"(r[3]) : "r"(addr));
}
__device__ __forceinline__ void cp_async16(unsigned smem_addr, const void* gptr) {
    asm volatile("cp.async.cg.shared.global [%0], [%1], 16;"
                 :: "r"(smem_addr), "l"(gptr));
}
__device__ __forceinline__ void cp_commit() {
    asm volatile("cp.async.commit_group;");
}

// ---------------------------------------------------------------------------
// Fused prepass: x->fp16 | qkv_w->fp16 | proj_w->fp16 | comb table
// ---------------------------------------------------------------------------
#define NB_X   25088   // M*CDIM/4 / 256
#define NB_WQ  (CDIM * THREECD / 4 / 256)   // 192
#define NB_WP  (CDIM * CDIM / 4 / 256)      // 64
#define NB_CB  (NW * NHEADS)                // 512
#define NB_TOTAL (NB_X + NB_WQ + NB_WP + NB_CB)

__global__ __launch_bounds__(256) void prepass_kernel(
    const float4* __restrict__ x4, uint2* __restrict__ xh4,
    const float4* __restrict__ wq4, uint2* __restrict__ wqh4,
    const float4* __restrict__ wp4, uint2* __restrict__ wph4,
    const float* __restrict__ mask, const float* __restrict__ bias_table,
    float* __restrict__ comb)
{
    const int bid = blockIdx.x;
    const int tid = threadIdx.x;

    if (bid < NB_X + NB_WQ + NB_WP) {
        const float4* src;
        uint2* dst;
        int idx;
        if (bid < NB_X) {
            src = x4; dst = xh4; idx = bid * 256 + tid;
        } else if (bid < NB_X + NB_WQ) {
            src = wq4; dst = wqh4; idx = (bid - NB_X) * 256 + tid;
        } else {
            src = wp4; dst = wph4; idx = (bid - NB_X - NB_WQ) * 256 + tid;
        }
        float4 v = src[idx];
        __half2 h0 = __floats2half2_rn(v.x, v.y);
        __half2 h1 = __floats2half2_rn(v.z, v.w);
        uint2 o;
        o.x = *(unsigned*)&h0;
        o.y = *(unsigned*)&h1;
        dst[idx] = o;
    } else {
        const int b2 = bid - NB_X - NB_WQ - NB_WP;
        const int w = b2 & (NW - 1), h = b2 >> 6;
        const float* mrow = mask + (size_t)w * NSEQ * NSEQ;
        float* crow = comb + ((size_t)w * NHEADS + h) * NSEQ * NSEQ;
        for (int p = tid; p < NSEQ * NSEQ; p += 256) {
            int i = p / NSEQ, j = p - (p / NSEQ) * NSEQ;
            int i0 = i / 7, i1 = i - i0 * 7;
            int j0 = j / 7, j1 = j - j0 * 7;
            int ridx = (i0 - j0 + 6) * 13 + (i1 - j1 + 6);
            crow[p] = mrow[p] + bias_table[ridx * NHEADS + h];
        }
    }
}

// ---------------------------------------------------------------------------
// FP16 tensor-core GEMM (round-10 proven config): C[M,N] = A[M,K] @ B[K,N] + bias
// CTA 128x128, BK=32, 8 warps (2m x 4n), warp tile 64x32. 4-stage cp.async.
// ---------------------------------------------------------------------------
#define GBM 128
#define GBN 128
#define GBK 32
#define ASTR 40
#define BSTR 136
#define STAGES 4
#define ABUF (GBM * ASTR * 2)
#define BBUF (GBK * BSTR * 2)
#define GEMM_SMEM (STAGES * (ABUF + BBUF))    // 75776 B

template <bool OUT_HALF>
__global__ __launch_bounds__(256, 2) void gemm_f16_kernel(
    const __half* __restrict__ A, const __half* __restrict__ B,
    const float* __restrict__ bias, void* __restrict__ Cv,
    int M, int K, int N)
{
    extern __shared__ __half sm[];
    __half* AsH = sm;
    __half* BsH = sm + STAGES * GBM * ASTR;

    const int tid  = threadIdx.x;
    const int wid  = tid >> 5;
    const int lane = tid & 31;
    const int wm   = wid & 1;
    const int wn   = wid >> 1;
    const int g    = lane >> 2;
    const int t    = lane & 3;
    const int rowC = blockIdx.y * GBM;
    const int colC = blockIdx.x * GBN;

    const __half* Aptr = A + (size_t)rowC * K;
    const __half* Bptr = B + colC;

    const int a_q0 = tid,        a_q1 = tid + 256;
    const int a_r0 = a_q0 >> 2,  a_c0 = (a_q0 & 3) * 8;
    const int a_r1 = a_q1 >> 2,  a_c1 = (a_q1 & 3) * 8;
    const int b_q0 = tid,        b_q1 = tid + 256;
    const int b_r0 = b_q0 >> 4,  b_c0 = (b_q0 & 15) * 8;
    const int b_r1 = b_q1 >> 4,  b_c1 = (b_q1 & 15) * 8;

    const unsigned asBase = (unsigned)__cvta_generic_to_shared(AsH);
    const unsigned bsBase = (unsigned)__cvta_generic_to_shared(BsH);
    const unsigned aOff0 = (unsigned)(a_r0 * ASTR + a_c0) * 2;
    const unsigned aOff1 = (unsigned)(a_r1 * ASTR + a_c1) * 2;
    const unsigned bOff0 = (unsigned)(b_r0 * BSTR + b_c0) * 2;
    const unsigned bOff1 = (unsigned)(b_r1 * BSTR + b_c1) * 2;

    const unsigned aFragBase = (unsigned)__cvta_generic_to_shared(
        &AsH[(wm * 64 + (lane & 15)) * ASTR + ((lane >> 4) << 3)]);
    const unsigned bFragBase = (unsigned)__cvta_generic_to_shared(
        &BsH[(lane & 15) * BSTR + wn * 32 + ((lane >> 4) << 3)]);

    float acc[4][4][4];
#pragma unroll
    for (int mt = 0; mt < 4; mt++)
#pragma unroll
        for (int nt = 0; nt < 4; nt++)
#pragma unroll
            for (int r = 0; r < 4; r++) acc[mt][nt][r] = 0.f;

    const int nk = K / GBK;   // 8

#pragma unroll
    for (int s = 0; s < STAGES - 1; s++) {
        const int k0 = s * GBK;
        cp_async16(asBase + s * ABUF + aOff0, Aptr + (size_t)a_r0 * K + k0 + a_c0);
        cp_async16(asBase + s * ABUF + aOff1, Aptr + (size_t)a_r1 * K + k0 + a_c1);
        cp_async16(bsBase + s * BBUF + bOff0, Bptr + (size_t)(k0 + b_r0) * N + b_c0);
        cp_async16(bsBase + s * BBUF + bOff1, Bptr + (size_t)(k0 + b_r1) * N + b_c1);
        cp_commit();
    }
    asm volatile("cp.async.wait_group %0;" :: "n"(STAGES - 2));
    __syncthreads();

    int buf = 0;
    for (int kt = 0; kt < nk; kt++) {
        if (kt + STAGES - 1 < nk) {
            const int k0 = (kt + STAGES - 1) * GBK;
            const unsigned sb = (unsigned)((kt + STAGES - 1) & (STAGES - 1));
            cp_async16(asBase + sb * ABUF + aOff0, Aptr + (size_t)a_r0 * K + k0 + a_c0);
            cp_async16(asBase + sb * ABUF + aOff1, Aptr + (size_t)a_r1 * K + k0 + a_c1);
            cp_async16(bsBase + sb * BBUF + bOff0, Bptr + (size_t)(k0 + b_r0) * N + b_c0);
            cp_async16(bsBase + sb * BBUF + bOff1, Bptr + (size_t)(k0 + b_r1) * N + b_c1);
        }
        cp_commit();

#pragma unroll
        for (int kc = 0; kc < 2; kc++) {
            unsigned af[4][4], bf[2][4];
#pragma unroll
            for (int mt = 0; mt < 4; mt++)
                ldsm4(af[mt], aFragBase + buf * ABUF + mt * (16 * ASTR * 2) + kc * 32);
#pragma unroll
            for (int db = 0; db < 2; db++)
                ldsm4t(bf[db], bFragBase + buf * BBUF + kc * (16 * BSTR * 2) + db * 32);
#pragma unroll
            for (int nt = 0; nt < 4; nt++) {
                const unsigned b0 = bf[nt >> 1][(nt & 1) * 2];
                const unsigned b1 = bf[nt >> 1][(nt & 1) * 2 + 1];
#pragma unroll
                for (int mt = 0; mt < 4; mt++)
                    mma_f16(acc[mt][nt], af[mt], b0, b1);
            }
        }

        asm volatile("cp.async.wait_group %0;" :: "n"(STAGES - 2));
        __syncthreads();
        buf = (buf + 1) & (STAGES - 1);
    }

#pragma unroll
    for (int mt = 0; mt < 4; mt++) {
        const int r0 = rowC + wm * 64 + mt * 16 + g;
#pragma unroll
        for (int nt = 0; nt < 4; nt++) {
            const int cc = colC + wn * 32 + nt * 8 + 2 * t;
            const float bb0 = bias[cc], bb1 = bias[cc + 1];
            if (OUT_HALF) {
                __half* C = (__half*)Cv;
                *(__half2*)&C[(size_t)r0 * N + cc] =
                    __floats2half2_rn(acc[mt][nt][0] + bb0, acc[mt][nt][1] + bb1);
                *(__half2*)&C[(size_t)(r0 + 8) * N + cc] =
                    __floats2half2_rn(acc[mt][nt][2] + bb0, acc[mt][nt][3] + bb1);
            } else {
                float* C = (float*)Cv;
                float2 o;
                o.x = acc[mt][nt][0] + bb0; o.y = acc[mt][nt][1] + bb1;
                *(float2*)&C[(size_t)r0 * N + cc] = o;
                o.x = acc[mt][nt][2] + bb0; o.y = acc[mt][nt][3] + bb1;
                *(float2*)&C[(size_t)(r0 + 8) * N + cc] = o;
            }
        }
    }
}

// ---------------------------------------------------------------------------
// FP16 tensor-core window attention: one CTA per (b, head-pair), 8 warps.
// comb for both heads staged into smem with a coalesced load (kills the 4x
// sector overfetch seen in ncu: L1 74.8%, DRAM 23.4% on this kernel).
// Dynamic smem: q/k/v/sch + 2x2401 floats = 68360 B, 3 CTAs/SM.
// Arithmetic identical to round 13 (bit-identical output).
// ---------------------------------------------------------------------------
#define QSTR 40
#define SCSTR 72
#define OFF_QS   0
#define OFF_KS   10240
#define OFF_VS   20480
#define OFF_SCH  30720
#define OFF_CBS  49152
#define ATTN_SMEM (OFF_CBS + 2 * NSEQ * NSEQ * 4)   // 68360 B

__global__ __launch_bounds__(256) void attn_mma_kernel(
    const __half* __restrict__ qkv, const float* __restrict__ comb,
    __half* __restrict__ out)
{
    extern __shared__ char smraw[];
    __half (*qs)[64][QSTR]  = (__half(*)[64][QSTR])(smraw + OFF_QS);
    __half (*ks)[64][QSTR]  = (__half(*)[64][QSTR])(smraw + OFF_KS);
    __half (*vs)[64][QSTR]  = (__half(*)[64][QSTR])(smraw + OFF_VS);
    __half (*sch)[64][SCSTR] = (__half(*)[64][SCSTR])(smraw + OFF_SCH);
    float* cbs = (float*)(smraw + OFF_CBS);   // [2][NSEQ*NSEQ]

    const int hp = blockIdx.x;    // head pair: 0..3
    const int b  = blockIdx.y;    // 0..2047

    const int tid  = threadIdx.x;
    const int lane = tid & 31;
    const int wid  = tid >> 5;     // 0..7
    const int hh   = wid >> 2;     // head within pair
    const int g    = lane >> 2;
    const int t    = lane & 3;
    const float scale = 0.17677669529663687f;  // 32^-0.5

    // ---- load q,k,v for both heads (contiguous 128B per row)
    const __half* base = qkv + (size_t)b * NSEQ * THREECD + hp * 2 * DHEAD;
    for (int f = tid; f < NSEQ * 16; f += 256) {
        int n = f >> 4, c = (f & 15) << 2;
        int h2 = c >> 5, cc = c & 31;
        const __half* row = base + (size_t)n * THREECD;
        *(uint2*)&qs[h2][n][cc] = *(const uint2*)(row + c);
        *(uint2*)&ks[h2][n][cc] = *(const uint2*)(row + CDIM + c);
        *(uint2*)&vs[h2][n][cc] = *(const uint2*)(row + 2 * CDIM + c);
    }
    for (int z = tid; z < 2 * 15 * QSTR; z += 256) {
        int h2 = z / (15 * QSTR), zz = z - h2 * 15 * QSTR;
        vs[h2][NSEQ + zz / QSTR][zz % QSTR] = __ushort_as_half(0);
    }
    // ---- stage comb for both heads (fully coalesced: rows contiguous in [w][h])
    {
        const float* cb0 = comb + ((size_t)(b & (NW - 1)) * NHEADS + hp * 2)
                                  * NSEQ * NSEQ;
        for (int p = tid; p < 2 * NSEQ * NSEQ; p += 256)
            cbs[p] = cb0[p];
    }
    __syncthreads();

    const int row = (wid & 3) * 16;
    const int r0 = row + g, r1 = r0 + 8;
    const int h = hp * 2 + hh;
    const float* cbh = cbs + hh * NSEQ * NSEQ;

    // ---- QK^T
    float c_sc[7][4];
#pragma unroll
    for (int nt = 0; nt < 7; nt++)
#pragma unroll
        for (int r = 0; r < 4; r++) c_sc[nt][r] = 0.f;

    const unsigned qAddr = (unsigned)__cvta_generic_to_shared(
        &qs[hh][row + (lane & 15)][(lane >> 4) << 3]);
    const unsigned kAddr = (unsigned)__cvta_generic_to_shared(
        &ks[hh][(lane & 7) + ((lane >> 4) << 3)][((lane >> 3) & 1) << 3]);

#pragma unroll
    for (int kc = 0; kc < 2; kc++) {
        const int k0 = kc * 16;
        unsigned a[4];
        ldsm4(a, qAddr + k0 * 2);
        unsigned bf[4][4];
#pragma unroll
        for (int jb = 0; jb < 4; jb++)
            ldsm4(bf[jb], kAddr + (jb * 16 * QSTR + k0) * 2);
#pragma unroll
        for (int nt = 0; nt < 7; nt++) {
            const unsigned b0 = bf[nt >> 1][(nt & 1) * 2];
            const unsigned b1 = bf[nt >> 1][(nt & 1) * 2 + 1];
            mma_f16(c_sc[nt], a, b0, b1);
        }
    }

    // ---- epilogue: scale + comb (from smem), warp-local softmax
    float mx0 = -1e30f, mx1 = -1e30f;
#pragma unroll
    for (int nt = 0; nt < 7; nt++) {
#pragma unroll
        for (int cx = 0; cx < 2; cx++) {
            const int cc = nt * 8 + 2 * t + cx;
            float v0 = (r0 < NSEQ && cc < NSEQ)
                     ? fmaf(c_sc[nt][cx], scale, cbh[r0 * NSEQ + cc]) : -1e30f;
            float v1 = (r1 < NSEQ && cc < NSEQ)
                     ? fmaf(c_sc[nt][2 + cx], scale, cbh[r1 * NSEQ + cc]) : -1e30f;
            c_sc[nt][cx] = v0;     mx0 = fmaxf(mx0, v0);
            c_sc[nt][2 + cx] = v1; mx1 = fmaxf(mx1, v1);
        }
    }
    mx0 = fmaxf(mx0, __shfl_xor_sync(0xffffffffu, mx0, 1));
    mx0 = fmaxf(mx0, __shfl_xor_sync(0xffffffffu, mx0, 2));
    mx1 = fmaxf(mx1, __shfl_xor_sync(0xffffffffu, mx1, 1));
    mx1 = fmaxf(mx1, __shfl_xor_sync(0xffffffffu, mx1, 2));

    float s0 = 0.f, s1 = 0.f;
#pragma unroll
    for (int nt = 0; nt < 7; nt++) {
#pragma unroll
        for (int cx = 0; cx < 2; cx++) {
            float e0 = __expf(c_sc[nt][cx] - mx0);
            float e1 = __expf(c_sc[nt][2 + cx] - mx1);
            c_sc[nt][cx] = e0;     s0 += e0;
            c_sc[nt][2 + cx] = e1; s1 += e1;
        }
    }
    s0 += __shfl_xor_sync(0xffffffffu, s0, 1);
    s0 += __shfl_xor_sync(0xffffffffu, s0, 2);
    s1 += __shfl_xor_sync(0xffffffffu, s1, 1);
    s1 += __shfl_xor_sync(0xffffffffu, s1, 2);
    const float inv0 = 1.f / s0, inv1 = 1.f / s1;

#pragma unroll
    for (int nt = 0; nt < 7; nt++) {
        const int cc = nt * 8 + 2 * t;
        float p00 = (cc     < NSEQ) ? c_sc[nt][0] * inv0 : 0.f;
        float p01 = (cc + 1 < NSEQ) ? c_sc[nt][1] * inv0 : 0.f;
        float p10 = (cc     < NSEQ) ? c_sc[nt][2] * inv1 : 0.f;
        float p11 = (cc + 1 < NSEQ) ? c_sc[nt][3] * inv1 : 0.f;
        *(__half2*)&sch[hh][r0][cc] = __floats2half2_rn(p00, p01);
        *(__half2*)&sch[hh][r1][cc] = __floats2half2_rn(p10, p11);
    }
    {
        const int cc = 56 + 2 * t;
        *(unsigned*)&sch[hh][r0][cc] = 0u;
        *(unsigned*)&sch[hh][r1][cc] = 0u;
    }
    __syncwarp();

    // ---- AV
    float c_o[4][4];
#pragma unroll
    for (int nt = 0; nt < 4; nt++)
#pragma unroll
        for (int r = 0; r < 4; r++) c_o[nt][r] = 0.f;

    const unsigned pAddr = (unsigned)__cvta_generic_to_shared(
        &sch[hh][row + (lane & 15)][(lane >> 4) << 3]);
    const unsigned vAddr = (unsigned)__cvta_generic_to_shared(
        &vs[hh][lane & 15][(lane >> 4) << 3]);

#pragma unroll
    for (int kc = 0; kc < 4; kc++) {
        const int k0 = kc * 16;
        unsigned ap[4];
        ldsm4(ap, pAddr + k0 * 2);
        unsigned bf[2][4];
#pragma unroll
        for (int db = 0; db < 2; db++)
            ldsm4t(bf[db], vAddr + (k0 * QSTR + db * 16) * 2);
#pragma unroll
        for (int nt = 0; nt < 4; nt++) {
            const unsigned b0 = bf[nt >> 1][(nt & 1) * 2];
            const unsigned b1 = bf[nt >> 1][(nt & 1) * 2 + 1];
            mma_f16(c_o[nt], ap, b0, b1);
        }
    }

    __half* obase = out + (size_t)b * NSEQ * CDIM + h * DHEAD;
#pragma unroll
    for (int nt = 0; nt < 4; nt++) {
        const int dd = nt * 8 + 2 * t;
        if (r0 < NSEQ)
            *(__half2*)&obase[(size_t)r0 * CDIM + dd] =
                __floats2half2_rn(c_o[nt][0], c_o[nt][1]);
        if (r1 < NSEQ)
            *(__half2*)&obase[(size_t)r1 * CDIM + dd] =
                __floats2half2_rn(c_o[nt][2], c_o[nt][3]);
    }
}

// ---------------------------------------------------------------------------
extern "C" void kernel_launch(void* const* d_in, const int* in_sizes, int n_in,
                              void* d_out, int out_size)
{
    const float* x          = (const float*)d_in[0];
    const float* mask       = (const float*)d_in[1];
    const float* qkv_w      = (const float*)d_in[2];
    const float* qkv_b      = (const float*)d_in[3];
    const float* proj_w     = (const float*)d_in[4];
    const float* proj_b     = (const float*)d_in[5];
    const float* bias_table = (const float*)d_in[6];
    float* out = (float*)d_out;

    __half *xh, *wqkvh, *wprojh, *qkvh, *aoh;
    float *comb_ptr;
    cudaGetSymbolAddress((void**)&xh, g_xh);
    cudaGetSymbolAddress((void**)&wqkvh, g_wqkvh);
    cudaGetSymbolAddress((void**)&wprojh, g_wprojh);
    cudaGetSymbolAddress((void**)&qkvh, g_qkvh);
    cudaGetSymbolAddress((void**)&aoh, g_aoh);
    cudaGetSymbolAddress((void**)&comb_ptr, g_comb);

    static bool attr_set = false;
    if (!attr_set) {
        cudaFuncSetAttribute(gemm_f16_kernel<true>,
                             cudaFuncAttributeMaxDynamicSharedMemorySize, GEMM_SMEM);
        cudaFuncSetAttribute(gemm_f16_kernel<false>,
                             cudaFuncAttributeMaxDynamicSharedMemorySize, GEMM_SMEM);
        cudaFuncSetAttribute(attn_mma_kernel,
                             cudaFuncAttributeMaxDynamicSharedMemorySize, ATTN_SMEM);
        attr_set = true;
    }

    const int M = B_TOT * NSEQ;  // 100352

    // 0) fused prepass
    prepass_kernel<<<NB_TOTAL, 256>>>(
        (const float4*)x, (uint2*)xh,
        (const float4*)qkv_w, (uint2*)wqkvh,
        (const float4*)proj_w, (uint2*)wprojh,
        mask, bias_table, comb_ptr);
    // 1) qkv = x @ qkv_w + qkv_b  -> fp16
    {
        dim3 grid(THREECD / GBN, M / GBM);
        gemm_f16_kernel<true><<<grid, 256, GEMM_SMEM>>>(xh, wqkvh, qkv_b, qkvh,
                                                        M, CDIM, THREECD);
    }
    // 2) window attention -> fp16 (2 heads per CTA, comb staged in smem)
    {
        dim3 grid(NHEADS / 2, B_TOT);
        attn_mma_kernel<<<grid, 256, ATTN_SMEM>>>(qkvh, comb_ptr, aoh);
    }
    // 3) out = attnout @ proj_w + proj_b -> fp32
    {
        dim3 grid(CDIM / GBN, M / GBM);
        gemm_f16_kernel<false><<<grid, 256, GEMM_SMEM>>>(aoh, wprojh, proj_b, out,
                                                         M, CDIM, CDIM);
    }
}

// round 16
// speedup vs baseline: 1.2362x; 1.2362x over previous
#include <cuda_runtime.h>
#include <cuda_fp16.h>
#include <cstdint>

// Problem constants
#define B_TOT   2048
#define NSEQ    49
#define CDIM    256
#define NHEADS  8
#define DHEAD   32
#define NW      64
#define THREECD 768

// Scratch (allocation-free rule: __device__ globals)
__device__ __align__(16) __half g_xh[(size_t)B_TOT * NSEQ * CDIM];       // x fp16
__device__ __align__(16) __half g_wqkvh[(size_t)CDIM * THREECD];         // qkv_w fp16
__device__ __align__(16) __half g_wprojh[(size_t)CDIM * CDIM];           // proj_w fp16
__device__ __align__(16) __half g_qkvh[(size_t)B_TOT * NSEQ * THREECD];  // qkv fp16
__device__ __align__(16) __half g_aoh[(size_t)B_TOT * NSEQ * CDIM];      // attn out fp16
__device__ float g_comb[(size_t)NW * NHEADS * NSEQ * NSEQ];              // bias+mask

// ---------------------------------------------------------------------------
// PTX helpers (legacy mma path — tcgen05 unavailable on sm_103 PTX target)
// ---------------------------------------------------------------------------
__device__ __forceinline__ void mma_f16(float (&c)[4], const unsigned (&a)[4],
                                        unsigned b0, unsigned b1) {
    asm volatile(
        "mma.sync.aligned.m16n8k16.row.col.f32.f16.f16.f32 "
        "{%0,%1,%2,%3}, {%4,%5,%6,%7}, {%8,%9}, {%0,%1,%2,%3};\n"
        : "+f"(c[0]), "+f"(c[1]), "+f"(c[2]), "+f"(c[3])
        : "r"(a[0]), "r"(a[1]), "r"(a[2]), "r"(a[3]), "r"(b0), "r"(b1));
}
__device__ __forceinline__ void ldsm4(unsigned (&r)[4], unsigned addr) {
    asm volatile("ldmatrix.sync.aligned.m8n8.x4.shared.b16 {%0,%1,%2,%3}, [%4];"
        : "=r"(r[0]), "=r"(r[1]), "=r"(r[2]), "=r"(r[3]) : "r"(addr));
}
__device__ __forceinline__ void ldsm4t(unsigned (&r)[4], unsigned addr) {
    asm volatile("ldmatrix.sync.aligned.m8n8.x4.trans.shared.b16 {%0,%1,%2,%3}, [%4];"
        : "=r"(r[0]), "=r"(r[1]), "=r"(r[2]), "=r"(r[3]) : "r"(addr));
}
__device__ __forceinline__ void cp_async16(unsigned smem_addr, const void* gptr) {
    asm volatile("cp.async.cg.shared.global [%0], [%1], 16;"
                 :: "r"(smem_addr), "l"(gptr));
}
__device__ __forceinline__ void cp_commit() {
    asm volatile("cp.async.commit_group;");
}

// ---------------------------------------------------------------------------
// Fused prepass: x->fp16 | qkv_w->fp16 | proj_w->fp16 | comb table
// ---------------------------------------------------------------------------
#define NB_X   25088   // M*CDIM/4 / 256
#define NB_WQ  (CDIM * THREECD / 4 / 256)   // 192
#define NB_WP  (CDIM * CDIM / 4 / 256)      // 64
#define NB_CB  (NW * NHEADS)                // 512
#define NB_TOTAL (NB_X + NB_WQ + NB_WP + NB_CB)

__global__ __launch_bounds__(256) void prepass_kernel(
    const float4* __restrict__ x4, uint2* __restrict__ xh4,
    const float4* __restrict__ wq4, uint2* __restrict__ wqh4,
    const float4* __restrict__ wp4, uint2* __restrict__ wph4,
    const float* __restrict__ mask, const float* __restrict__ bias_table,
    float* __restrict__ comb)
{
    const int bid = blockIdx.x;
    const int tid = threadIdx.x;

    if (bid < NB_X + NB_WQ + NB_WP) {
        const float4* src;
        uint2* dst;
        int idx;
        if (bid < NB_X) {
            src = x4; dst = xh4; idx = bid * 256 + tid;
        } else if (bid < NB_X + NB_WQ) {
            src = wq4; dst = wqh4; idx = (bid - NB_X) * 256 + tid;
        } else {
            src = wp4; dst = wph4; idx = (bid - NB_X - NB_WQ) * 256 + tid;
        }
        float4 v = src[idx];
        __half2 h0 = __floats2half2_rn(v.x, v.y);
        __half2 h1 = __floats2half2_rn(v.z, v.w);
        uint2 o;
        o.x = *(unsigned*)&h0;
        o.y = *(unsigned*)&h1;
        dst[idx] = o;
    } else {
        const int b2 = bid - NB_X - NB_WQ - NB_WP;
        const int w = b2 & (NW - 1), h = b2 >> 6;
        const float* mrow = mask + (size_t)w * NSEQ * NSEQ;
        float* crow = comb + ((size_t)w * NHEADS + h) * NSEQ * NSEQ;
        for (int p = tid; p < NSEQ * NSEQ; p += 256) {
            int i = p / NSEQ, j = p - (p / NSEQ) * NSEQ;
            int i0 = i / 7, i1 = i - i0 * 7;
            int j0 = j / 7, j1 = j - j0 * 7;
            int ridx = (i0 - j0 + 6) * 13 + (i1 - j1 + 6);
            crow[p] = mrow[p] + bias_table[ridx * NHEADS + h];
        }
    }
}

// ---------------------------------------------------------------------------
// FP16 tensor-core GEMM (round-10 proven config): C[M,N] = A[M,K] @ B[K,N] + bias
// CTA 128x128, BK=32, 8 warps (2m x 4n), warp tile 64x32. 4-stage cp.async.
// ---------------------------------------------------------------------------
#define GBM 128
#define GBN 128
#define GBK 32
#define ASTR 40
#define BSTR 136
#define STAGES 4
#define ABUF (GBM * ASTR * 2)
#define BBUF (GBK * BSTR * 2)
#define GEMM_SMEM (STAGES * (ABUF + BBUF))    // 75776 B

template <bool OUT_HALF>
__global__ __launch_bounds__(256, 2) void gemm_f16_kernel(
    const __half* __restrict__ A, const __half* __restrict__ B,
    const float* __restrict__ bias, void* __restrict__ Cv,
    int M, int K, int N)
{
    extern __shared__ __half sm[];
    __half* AsH = sm;
    __half* BsH = sm + STAGES * GBM * ASTR;

    const int tid  = threadIdx.x;
    const int wid  = tid >> 5;
    const int lane = tid & 31;
    const int wm   = wid & 1;
    const int wn   = wid >> 1;
    const int g    = lane >> 2;
    const int t    = lane & 3;
    const int rowC = blockIdx.y * GBM;
    const int colC = blockIdx.x * GBN;

    const __half* Aptr = A + (size_t)rowC * K;
    const __half* Bptr = B + colC;

    const int a_q0 = tid,        a_q1 = tid + 256;
    const int a_r0 = a_q0 >> 2,  a_c0 = (a_q0 & 3) * 8;
    const int a_r1 = a_q1 >> 2,  a_c1 = (a_q1 & 3) * 8;
    const int b_q0 = tid,        b_q1 = tid + 256;
    const int b_r0 = b_q0 >> 4,  b_c0 = (b_q0 & 15) * 8;
    const int b_r1 = b_q1 >> 4,  b_c1 = (b_q1 & 15) * 8;

    const unsigned asBase = (unsigned)__cvta_generic_to_shared(AsH);
    const unsigned bsBase = (unsigned)__cvta_generic_to_shared(BsH);
    const unsigned aOff0 = (unsigned)(a_r0 * ASTR + a_c0) * 2;
    const unsigned aOff1 = (unsigned)(a_r1 * ASTR + a_c1) * 2;
    const unsigned bOff0 = (unsigned)(b_r0 * BSTR + b_c0) * 2;
    const unsigned bOff1 = (unsigned)(b_r1 * BSTR + b_c1) * 2;

    const unsigned aFragBase = (unsigned)__cvta_generic_to_shared(
        &AsH[(wm * 64 + (lane & 15)) * ASTR + ((lane >> 4) << 3)]);
    const unsigned bFragBase = (unsigned)__cvta_generic_to_shared(
        &BsH[(lane & 15) * BSTR + wn * 32 + ((lane >> 4) << 3)]);

    float acc[4][4][4];
#pragma unroll
    for (int mt = 0; mt < 4; mt++)
#pragma unroll
        for (int nt = 0; nt < 4; nt++)
#pragma unroll
            for (int r = 0; r < 4; r++) acc[mt][nt][r] = 0.f;

    const int nk = K / GBK;   // 8

#pragma unroll
    for (int s = 0; s < STAGES - 1; s++) {
        const int k0 = s * GBK;
        cp_async16(asBase + s * ABUF + aOff0, Aptr + (size_t)a_r0 * K + k0 + a_c0);
        cp_async16(asBase + s * ABUF + aOff1, Aptr + (size_t)a_r1 * K + k0 + a_c1);
        cp_async16(bsBase + s * BBUF + bOff0, Bptr + (size_t)(k0 + b_r0) * N + b_c0);
        cp_async16(bsBase + s * BBUF + bOff1, Bptr + (size_t)(k0 + b_r1) * N + b_c1);
        cp_commit();
    }
    asm volatile("cp.async.wait_group %0;" :: "n"(STAGES - 2));
    __syncthreads();

    int buf = 0;
    for (int kt = 0; kt < nk; kt++) {
        if (kt + STAGES - 1 < nk) {
            const int k0 = (kt + STAGES - 1) * GBK;
            const unsigned sb = (unsigned)((kt + STAGES - 1) & (STAGES - 1));
            cp_async16(asBase + sb * ABUF + aOff0, Aptr + (size_t)a_r0 * K + k0 + a_c0);
            cp_async16(asBase + sb * ABUF + aOff1, Aptr + (size_t)a_r1 * K + k0 + a_c1);
            cp_async16(bsBase + sb * BBUF + bOff0, Bptr + (size_t)(k0 + b_r0) * N + b_c0);
            cp_async16(bsBase + sb * BBUF + bOff1, Bptr + (size_t)(k0 + b_r1) * N + b_c1);
        }
        cp_commit();

#pragma unroll
        for (int kc = 0; kc < 2; kc++) {
            unsigned af[4][4], bf[2][4];
#pragma unroll
            for (int mt = 0; mt < 4; mt++)
                ldsm4(af[mt], aFragBase + buf * ABUF + mt * (16 * ASTR * 2) + kc * 32);
#pragma unroll
            for (int db = 0; db < 2; db++)
                ldsm4t(bf[db], bFragBase + buf * BBUF + kc * (16 * BSTR * 2) + db * 32);
#pragma unroll
            for (int nt = 0; nt < 4; nt++) {
                const unsigned b0 = bf[nt >> 1][(nt & 1) * 2];
                const unsigned b1 = bf[nt >> 1][(nt & 1) * 2 + 1];
#pragma unroll
                for (int mt = 0; mt < 4; mt++)
                    mma_f16(acc[mt][nt], af[mt], b0, b1);
            }
        }

        asm volatile("cp.async.wait_group %0;" :: "n"(STAGES - 2));
        __syncthreads();
        buf = (buf + 1) & (STAGES - 1);
    }

#pragma unroll
    for (int mt = 0; mt < 4; mt++) {
        const int r0 = rowC + wm * 64 + mt * 16 + g;
#pragma unroll
        for (int nt = 0; nt < 4; nt++) {
            const int cc = colC + wn * 32 + nt * 8 + 2 * t;
            const float bb0 = bias[cc], bb1 = bias[cc + 1];
            if (OUT_HALF) {
                __half* C = (__half*)Cv;
                *(__half2*)&C[(size_t)r0 * N + cc] =
                    __floats2half2_rn(acc[mt][nt][0] + bb0, acc[mt][nt][1] + bb1);
                *(__half2*)&C[(size_t)(r0 + 8) * N + cc] =
                    __floats2half2_rn(acc[mt][nt][2] + bb0, acc[mt][nt][3] + bb1);
            } else {
                float* C = (float*)Cv;
                float2 o;
                o.x = acc[mt][nt][0] + bb0; o.y = acc[mt][nt][1] + bb1;
                *(float2*)&C[(size_t)r0 * N + cc] = o;
                o.x = acc[mt][nt][2] + bb0; o.y = acc[mt][nt][3] + bb1;
                *(float2*)&C[(size_t)(r0 + 8) * N + cc] = o;
            }
        }
    }
}

// ---------------------------------------------------------------------------
// FP16 tensor-core window attention: one CTA per (b, head-pair), 8 warps.
// P never touches smem: the softmax accumulator layout maps directly onto the
// m16n8k16 A-fragment layout (a0=(g,2t), a1=(g+8,2t), a2=(g,8+2t), a3=(g+8,8+2t)),
// so AV chunk kc uses half2-packed P of nt=2kc / 2kc+1 (nt=7 -> 0).
// Removes 28 STS + 4 LDSM per warp and the 18KB sch smem array.
// Values and MMA order identical to round 13 -> bit-identical output.
// ---------------------------------------------------------------------------
#define QSTR 40

__global__ __launch_bounds__(256) void attn_mma_kernel(
    const __half* __restrict__ qkv, const float* __restrict__ comb,
    __half* __restrict__ out)
{
    const int hp = blockIdx.x;    // head pair: 0..3
    const int b  = blockIdx.y;    // 0..2047

    __shared__ __half qs[2][64][QSTR];
    __shared__ __half ks[2][64][QSTR];
    __shared__ __half vs[2][64][QSTR];

    const int tid  = threadIdx.x;
    const int lane = tid & 31;
    const int wid  = tid >> 5;     // 0..7
    const int hh   = wid >> 2;     // head within pair
    const int g    = lane >> 2;
    const int t    = lane & 3;
    const float scale = 0.17677669529663687f;  // 32^-0.5

    // ---- load q,k,v for both heads (contiguous 128B per row)
    const __half* base = qkv + (size_t)b * NSEQ * THREECD + hp * 2 * DHEAD;
    for (int f = tid; f < NSEQ * 16; f += 256) {
        int n = f >> 4, c = (f & 15) << 2;
        int h2 = c >> 5, cc = c & 31;
        const __half* row = base + (size_t)n * THREECD;
        *(uint2*)&qs[h2][n][cc] = *(const uint2*)(row + c);
        *(uint2*)&ks[h2][n][cc] = *(const uint2*)(row + CDIM + c);
        *(uint2*)&vs[h2][n][cc] = *(const uint2*)(row + 2 * CDIM + c);
    }
    for (int z = tid; z < 2 * 15 * QSTR; z += 256) {
        int h2 = z / (15 * QSTR), zz = z - h2 * 15 * QSTR;
        vs[h2][NSEQ + zz / QSTR][zz % QSTR] = __ushort_as_half(0);
    }
    __syncthreads();

    const int row = (wid & 3) * 16;
    const int r0 = row + g, r1 = r0 + 8;
    const int h = hp * 2 + hh;
    const float* cb = comb + ((size_t)(b & (NW - 1)) * NHEADS + h) * NSEQ * NSEQ;

    // ---- prefetch comb values (overlaps with QK^T MMA phase)
    float cA[14], cB[14];
#pragma unroll
    for (int nt = 0; nt < 7; nt++) {
#pragma unroll
        for (int cx = 0; cx < 2; cx++) {
            const int cc = nt * 8 + 2 * t + cx;
            cA[nt * 2 + cx] = (r0 < NSEQ && cc < NSEQ) ? cb[r0 * NSEQ + cc] : 0.f;
            cB[nt * 2 + cx] = (r1 < NSEQ && cc < NSEQ) ? cb[r1 * NSEQ + cc] : 0.f;
        }
    }

    // ---- QK^T
    float c_sc[7][4];
#pragma unroll
    for (int nt = 0; nt < 7; nt++)
#pragma unroll
        for (int r = 0; r < 4; r++) c_sc[nt][r] = 0.f;

    const unsigned qAddr = (unsigned)__cvta_generic_to_shared(
        &qs[hh][row + (lane & 15)][(lane >> 4) << 3]);
    const unsigned kAddr = (unsigned)__cvta_generic_to_shared(
        &ks[hh][(lane & 7) + ((lane >> 4) << 3)][((lane >> 3) & 1) << 3]);

#pragma unroll
    for (int kc = 0; kc < 2; kc++) {
        const int k0 = kc * 16;
        unsigned a[4];
        ldsm4(a, qAddr + k0 * 2);
        unsigned bf[4][4];
#pragma unroll
        for (int jb = 0; jb < 4; jb++)
            ldsm4(bf[jb], kAddr + (jb * 16 * QSTR + k0) * 2);
#pragma unroll
        for (int nt = 0; nt < 7; nt++) {
            const unsigned b0 = bf[nt >> 1][(nt & 1) * 2];
            const unsigned b1 = bf[nt >> 1][(nt & 1) * 2 + 1];
            mma_f16(c_sc[nt], a, b0, b1);
        }
    }

    // ---- epilogue: scale + comb, warp-local softmax
    float mx0 = -1e30f, mx1 = -1e30f;
#pragma unroll
    for (int nt = 0; nt < 7; nt++) {
#pragma unroll
        for (int cx = 0; cx < 2; cx++) {
            const int cc = nt * 8 + 2 * t + cx;
            float v0 = (r0 < NSEQ && cc < NSEQ)
                     ? fmaf(c_sc[nt][cx], scale, cA[nt * 2 + cx]) : -1e30f;
            float v1 = (r1 < NSEQ && cc < NSEQ)
                     ? fmaf(c_sc[nt][2 + cx], scale, cB[nt * 2 + cx]) : -1e30f;
            c_sc[nt][cx] = v0;     mx0 = fmaxf(mx0, v0);
            c_sc[nt][2 + cx] = v1; mx1 = fmaxf(mx1, v1);
        }
    }
    mx0 = fmaxf(mx0, __shfl_xor_sync(0xffffffffu, mx0, 1));
    mx0 = fmaxf(mx0, __shfl_xor_sync(0xffffffffu, mx0, 2));
    mx1 = fmaxf(mx1, __shfl_xor_sync(0xffffffffu, mx1, 1));
    mx1 = fmaxf(mx1, __shfl_xor_sync(0xffffffffu, mx1, 2));

    float s0 = 0.f, s1 = 0.f;
#pragma unroll
    for (int nt = 0; nt < 7; nt++) {
#pragma unroll
        for (int cx = 0; cx < 2; cx++) {
            float e0 = __expf(c_sc[nt][cx] - mx0);
            float e1 = __expf(c_sc[nt][2 + cx] - mx1);
            c_sc[nt][cx] = e0;     s0 += e0;
            c_sc[nt][2 + cx] = e1; s1 += e1;
        }
    }
    s0 += __shfl_xor_sync(0xffffffffu, s0, 1);
    s0 += __shfl_xor_sync(0xffffffffu, s0, 2);
    s1 += __shfl_xor_sync(0xffffffffu, s1, 1);
    s1 += __shfl_xor_sync(0xffffffffu, s1, 2);
    const float inv0 = 1.f / s0, inv1 = 1.f / s1;

    // ---- normalized P straight into A-fragment registers (no smem)
    unsigned ph0[7], ph1[7];   // ph0[nt] = rows r0, cols nt*8+2t..+1; ph1 = r1
#pragma unroll
    for (int nt = 0; nt < 7; nt++) {
        const int cc = nt * 8 + 2 * t;
        float p00 = (cc     < NSEQ) ? c_sc[nt][0] * inv0 : 0.f;
        float p01 = (cc + 1 < NSEQ) ? c_sc[nt][1] * inv0 : 0.f;
        float p10 = (cc     < NSEQ) ? c_sc[nt][2] * inv1 : 0.f;
        float p11 = (cc + 1 < NSEQ) ? c_sc[nt][3] * inv1 : 0.f;
        __half2 h0 = __floats2half2_rn(p00, p01);
        __half2 h1 = __floats2half2_rn(p10, p11);
        ph0[nt] = *(unsigned*)&h0;
        ph1[nt] = *(unsigned*)&h1;
    }

    // ---- AV: A-fragments from registers, V fragments via ldsm.trans
    float c_o[4][4];
#pragma unroll
    for (int nt = 0; nt < 4; nt++)
#pragma unroll
        for (int r = 0; r < 4; r++) c_o[nt][r] = 0.f;

    const unsigned vAddr = (unsigned)__cvta_generic_to_shared(
        &vs[hh][lane & 15][(lane >> 4) << 3]);

#pragma unroll
    for (int kc = 0; kc < 4; kc++) {
        const int k0 = kc * 16;
        unsigned ap[4];
        ap[0] = ph0[2 * kc];
        ap[1] = ph1[2 * kc];
        ap[2] = (2 * kc + 1 < 7) ? ph0[2 * kc + 1] : 0u;
        ap[3] = (2 * kc + 1 < 7) ? ph1[2 * kc + 1] : 0u;
        unsigned bf[2][4];
#pragma unroll
        for (int db = 0; db < 2; db++)
            ldsm4t(bf[db], vAddr + (k0 * QSTR + db * 16) * 2);
#pragma unroll
        for (int nt = 0; nt < 4; nt++) {
            const unsigned b0 = bf[nt >> 1][(nt & 1) * 2];
            const unsigned b1 = bf[nt >> 1][(nt & 1) * 2 + 1];
            mma_f16(c_o[nt], ap, b0, b1);
        }
    }

    __half* obase = out + (size_t)b * NSEQ * CDIM + h * DHEAD;
#pragma unroll
    for (int nt = 0; nt < 4; nt++) {
        const int dd = nt * 8 + 2 * t;
        if (r0 < NSEQ)
            *(__half2*)&obase[(size_t)r0 * CDIM + dd] =
                __floats2half2_rn(c_o[nt][0], c_o[nt][1]);
        if (r1 < NSEQ)
            *(__half2*)&obase[(size_t)r1 * CDIM + dd] =
                __floats2half2_rn(c_o[nt][2], c_o[nt][3]);
    }
}

// ---------------------------------------------------------------------------
extern "C" void kernel_launch(void* const* d_in, const int* in_sizes, int n_in,
                              void* d_out, int out_size)
{
    const float* x          = (const float*)d_in[0];
    const float* mask       = (const float*)d_in[1];
    const float* qkv_w      = (const float*)d_in[2];
    const float* qkv_b      = (const float*)d_in[3];
    const float* proj_w     = (const float*)d_in[4];
    const float* proj_b     = (const float*)d_in[5];
    const float* bias_table = (const float*)d_in[6];
    float* out = (float*)d_out;

    __half *xh, *wqkvh, *wprojh, *qkvh, *aoh;
    float *comb_ptr;
    cudaGetSymbolAddress((void**)&xh, g_xh);
    cudaGetSymbolAddress((void**)&wqkvh, g_wqkvh);
    cudaGetSymbolAddress((void**)&wprojh, g_wprojh);
    cudaGetSymbolAddress((void**)&qkvh, g_qkvh);
    cudaGetSymbolAddress((void**)&aoh, g_aoh);
    cudaGetSymbolAddress((void**)&comb_ptr, g_comb);

    static bool attr_set = false;
    if (!attr_set) {
        cudaFuncSetAttribute(gemm_f16_kernel<true>,
                             cudaFuncAttributeMaxDynamicSharedMemorySize, GEMM_SMEM);
        cudaFuncSetAttribute(gemm_f16_kernel<false>,
                             cudaFuncAttributeMaxDynamicSharedMemorySize, GEMM_SMEM);
        attr_set = true;
    }

    const int M = B_TOT * NSEQ;  // 100352

    // 0) fused prepass
    prepass_kernel<<<NB_TOTAL, 256>>>(
        (const float4*)x, (uint2*)xh,
        (const float4*)qkv_w, (uint2*)wqkvh,
        (const float4*)proj_w, (uint2*)wprojh,
        mask, bias_table, comb_ptr);
    // 1) qkv = x @ qkv_w + qkv_b  -> fp16
    {
        dim3 grid(THREECD / GBN, M / GBM);
        gemm_f16_kernel<true><<<grid, 256, GEMM_SMEM>>>(xh, wqkvh, qkv_b, qkvh,
                                                        M, CDIM, THREECD);
    }
    // 2) window attention -> fp16 (2 heads per CTA, register-resident P)
    {
        dim3 grid(NHEADS / 2, B_TOT);
        attn_mma_kernel<<<grid, 256>>>(qkvh, comb_ptr, aoh);
    }
    // 3) out = attnout @ proj_w + proj_b -> fp32
    {
        dim3 grid(CDIM / GBN, M / GBM);
        gemm_f16_kernel<false><<<grid, 256, GEMM_SMEM>>>(aoh, wprojh, proj_b, out,
                                                         M, CDIM, CDIM);
    }
}

// round 17
// speedup vs baseline: 1.2452x; 1.0073x over previous
#include <cuda_runtime.h>
#include <cuda_fp16.h>
#include <cstdint>

// Problem constants
#define B_TOT   2048
#define NSEQ    49
#define CDIM    256
#define NHEADS  8
#define DHEAD   32
#define NW      64
#define THREECD 768

// Scratch (allocation-free rule: __device__ globals)
__device__ __align__(16) __half g_xh[(size_t)B_TOT * NSEQ * CDIM];       // x fp16
__device__ __align__(16) __half g_wqkvh[(size_t)CDIM * THREECD];         // qkv_w fp16
__device__ __align__(16) __half g_wprojh[(size_t)CDIM * CDIM];           // proj_w fp16
__device__ __align__(16) __half g_aoh[(size_t)B_TOT * NSEQ * CDIM];      // attn out fp16
__device__ float g_comb[(size_t)NW * NHEADS * NSEQ * NSEQ];              // bias+mask

// ---------------------------------------------------------------------------
// PTX helpers (legacy mma path — tcgen05 unavailable on sm_103 PTX target)
// ---------------------------------------------------------------------------
__device__ __forceinline__ void mma_f16(float (&c)[4], const unsigned (&a)[4],
                                        unsigned b0, unsigned b1) {
    asm volatile(
        "mma.sync.aligned.m16n8k16.row.col.f32.f16.f16.f32 "
        "{%0,%1,%2,%3}, {%4,%5,%6,%7}, {%8,%9}, {%0,%1,%2,%3};\n"
        : "+f"(c[0]), "+f"(c[1]), "+f"(c[2]), "+f"(c[3])
        : "r"(a[0]), "r"(a[1]), "r"(a[2]), "r"(a[3]), "r"(b0), "r"(b1));
}
__device__ __forceinline__ void ldsm4(unsigned (&r)[4], unsigned addr) {
    asm volatile("ldmatrix.sync.aligned.m8n8.x4.shared.b16 {%0,%1,%2,%3}, [%4];"
        : "=r"(r[0]), "=r"(r[1]), "=r"(r[2]), "=r"(r[3]) : "r"(addr));
}
__device__ __forceinline__ void ldsm4t(unsigned (&r)[4], unsigned addr) {
    asm volatile("ldmatrix.sync.aligned.m8n8.x4.trans.shared.b16 {%0,%1,%2,%3}, [%4];"
        : "=r"(r[0]), "=r"(r[1]), "=r"(r[2]), "=r"(r[3]) : "r"(addr));
}
__device__ __forceinline__ void cp_async16(unsigned smem_addr, const void* gptr) {
    asm volatile("cp.async.cg.shared.global [%0], [%1], 16;"
                 :: "r"(smem_addr), "l"(gptr));
}
__device__ __forceinline__ void cp_commit() {
    asm volatile("cp.async.commit_group;");
}

// ---------------------------------------------------------------------------
// Fused prepass: x->fp16 | qkv_w->fp16 | proj_w->fp16 | comb table
// ---------------------------------------------------------------------------
#define NB_X   25088
#define NB_WQ  (CDIM * THREECD / 4 / 256)   // 192
#define NB_WP  (CDIM * CDIM / 4 / 256)      // 64
#define NB_CB  (NW * NHEADS)                // 512
#define NB_TOTAL (NB_X + NB_WQ + NB_WP + NB_CB)

__global__ __launch_bounds__(256) void prepass_kernel(
    const float4* __restrict__ x4, uint2* __restrict__ xh4,
    const float4* __restrict__ wq4, uint2* __restrict__ wqh4,
    const float4* __restrict__ wp4, uint2* __restrict__ wph4,
    const float* __restrict__ mask, const float* __restrict__ bias_table,
    float* __restrict__ comb)
{
    const int bid = blockIdx.x;
    const int tid = threadIdx.x;

    if (bid < NB_X + NB_WQ + NB_WP) {
        const float4* src;
        uint2* dst;
        int idx;
        if (bid < NB_X) {
            src = x4; dst = xh4; idx = bid * 256 + tid;
        } else if (bid < NB_X + NB_WQ) {
            src = wq4; dst = wqh4; idx = (bid - NB_X) * 256 + tid;
        } else {
            src = wp4; dst = wph4; idx = (bid - NB_X - NB_WQ) * 256 + tid;
        }
        float4 v = src[idx];
        __half2 h0 = __floats2half2_rn(v.x, v.y);
        __half2 h1 = __floats2half2_rn(v.z, v.w);
        uint2 o;
        o.x = *(unsigned*)&h0;
        o.y = *(unsigned*)&h1;
        dst[idx] = o;
    } else {
        const int b2 = bid - NB_X - NB_WQ - NB_WP;
        const int w = b2 & (NW - 1), h = b2 >> 6;
        const float* mrow = mask + (size_t)w * NSEQ * NSEQ;
        float* crow = comb + ((size_t)w * NHEADS + h) * NSEQ * NSEQ;
        for (int p = tid; p < NSEQ * NSEQ; p += 256) {
            int i = p / NSEQ, j = p - (p / NSEQ) * NSEQ;
            int i0 = i / 7, i1 = i - i0 * 7;
            int j0 = j / 7, j1 = j - j0 * 7;
            int ridx = (i0 - j0 + 6) * 13 + (i1 - j1 + 6);
            crow[p] = mrow[p] + bias_table[ridx * NHEADS + h];
        }
    }
}

// ---------------------------------------------------------------------------
// FP16 tensor-core GEMM (round-10 proven config) — used for proj only.
// ---------------------------------------------------------------------------
#define GBM 128
#define GBN 128
#define GBK 32
#define ASTR 40
#define BSTR 136
#define STAGES 4
#define ABUF (GBM * ASTR * 2)
#define BBUF (GBK * BSTR * 2)
#define GEMM_SMEM (STAGES * (ABUF + BBUF))    // 75776 B

__global__ __launch_bounds__(256, 2) void gemm_f16_kernel(
    const __half* __restrict__ A, const __half* __restrict__ B,
    const float* __restrict__ bias, float* __restrict__ C,
    int M, int K, int N)
{
    extern __shared__ __half sm[];
    __half* AsH = sm;
    __half* BsH = sm + STAGES * GBM * ASTR;

    const int tid  = threadIdx.x;
    const int wid  = tid >> 5;
    const int lane = tid & 31;
    const int wm   = wid & 1;
    const int wn   = wid >> 1;
    const int g    = lane >> 2;
    const int t    = lane & 3;
    const int rowC = blockIdx.y * GBM;
    const int colC = blockIdx.x * GBN;

    const __half* Aptr = A + (size_t)rowC * K;
    const __half* Bptr = B + colC;

    const int a_q0 = tid,        a_q1 = tid + 256;
    const int a_r0 = a_q0 >> 2,  a_c0 = (a_q0 & 3) * 8;
    const int a_r1 = a_q1 >> 2,  a_c1 = (a_q1 & 3) * 8;
    const int b_q0 = tid,        b_q1 = tid + 256;
    const int b_r0 = b_q0 >> 4,  b_c0 = (b_q0 & 15) * 8;
    const int b_r1 = b_q1 >> 4,  b_c1 = (b_q1 & 15) * 8;

    const unsigned asBase = (unsigned)__cvta_generic_to_shared(AsH);
    const unsigned bsBase = (unsigned)__cvta_generic_to_shared(BsH);
    const unsigned aOff0 = (unsigned)(a_r0 * ASTR + a_c0) * 2;
    const unsigned aOff1 = (unsigned)(a_r1 * ASTR + a_c1) * 2;
    const unsigned bOff0 = (unsigned)(b_r0 * BSTR + b_c0) * 2;
    const unsigned bOff1 = (unsigned)(b_r1 * BSTR + b_c1) * 2;

    const unsigned aFragBase = (unsigned)__cvta_generic_to_shared(
        &AsH[(wm * 64 + (lane & 15)) * ASTR + ((lane >> 4) << 3)]);
    const unsigned bFragBase = (unsigned)__cvta_generic_to_shared(
        &BsH[(lane & 15) * BSTR + wn * 32 + ((lane >> 4) << 3)]);

    float acc[4][4][4];
#pragma unroll
    for (int mt = 0; mt < 4; mt++)
#pragma unroll
        for (int nt = 0; nt < 4; nt++)
#pragma unroll
            for (int r = 0; r < 4; r++) acc[mt][nt][r] = 0.f;

    const int nk = K / GBK;

#pragma unroll
    for (int s = 0; s < STAGES - 1; s++) {
        const int k0 = s * GBK;
        cp_async16(asBase + s * ABUF + aOff0, Aptr + (size_t)a_r0 * K + k0 + a_c0);
        cp_async16(asBase + s * ABUF + aOff1, Aptr + (size_t)a_r1 * K + k0 + a_c1);
        cp_async16(bsBase + s * BBUF + bOff0, Bptr + (size_t)(k0 + b_r0) * N + b_c0);
        cp_async16(bsBase + s * BBUF + bOff1, Bptr + (size_t)(k0 + b_r1) * N + b_c1);
        cp_commit();
    }
    asm volatile("cp.async.wait_group %0;" :: "n"(STAGES - 2));
    __syncthreads();

    int buf = 0;
    for (int kt = 0; kt < nk; kt++) {
        if (kt + STAGES - 1 < nk) {
            const int k0 = (kt + STAGES - 1) * GBK;
            const unsigned sb = (unsigned)((kt + STAGES - 1) & (STAGES - 1));
            cp_async16(asBase + sb * ABUF + aOff0, Aptr + (size_t)a_r0 * K + k0 + a_c0);
            cp_async16(asBase + sb * ABUF + aOff1, Aptr + (size_t)a_r1 * K + k0 + a_c1);
            cp_async16(bsBase + sb * BBUF + bOff0, Bptr + (size_t)(k0 + b_r0) * N + b_c0);
            cp_async16(bsBase + sb * BBUF + bOff1, Bptr + (size_t)(k0 + b_r1) * N + b_c1);
        }
        cp_commit();

#pragma unroll
        for (int kc = 0; kc < 2; kc++) {
            unsigned af[4][4], bf[2][4];
#pragma unroll
            for (int mt = 0; mt < 4; mt++)
                ldsm4(af[mt], aFragBase + buf * ABUF + mt * (16 * ASTR * 2) + kc * 32);
#pragma unroll
            for (int db = 0; db < 2; db++)
                ldsm4t(bf[db], bFragBase + buf * BBUF + kc * (16 * BSTR * 2) + db * 32);
#pragma unroll
            for (int nt = 0; nt < 4; nt++) {
                const unsigned b0 = bf[nt >> 1][(nt & 1) * 2];
                const unsigned b1 = bf[nt >> 1][(nt & 1) * 2 + 1];
#pragma unroll
                for (int mt = 0; mt < 4; mt++)
                    mma_f16(acc[mt][nt], af[mt], b0, b1);
            }
        }

        asm volatile("cp.async.wait_group %0;" :: "n"(STAGES - 2));
        __syncthreads();
        buf = (buf + 1) & (STAGES - 1);
    }

#pragma unroll
    for (int mt = 0; mt < 4; mt++) {
        const int r0 = rowC + wm * 64 + mt * 16 + g;
#pragma unroll
        for (int nt = 0; nt < 4; nt++) {
            const int cc = colC + wn * 32 + nt * 8 + 2 * t;
            const float bb0 = bias[cc], bb1 = bias[cc + 1];
            float2 o;
            o.x = acc[mt][nt][0] + bb0; o.y = acc[mt][nt][1] + bb1;
            *(float2*)&C[(size_t)r0 * N + cc] = o;
            o.x = acc[mt][nt][2] + bb0; o.y = acc[mt][nt][3] + bb1;
            *(float2*)&C[(size_t)(r0 + 8) * N + cc] = o;
        }
    }
}

// ---------------------------------------------------------------------------
// FUSED qkv-GEMM + window attention. One CTA per (head-pair, b), 8 warps.
// Phase 1: qkv[49,192] = x[49,256] @ Wslice[256,192] (+bias), accumulated with
//   the same BK=32 / 2x-k16 chain as gemm_f16_kernel (bit-identical values),
//   epilogue written as fp16 directly into smem q/k/v arrays.
// Phase 2: round-16 attention (register-resident P), unchanged.
// Eliminates the 308MB qkv DRAM round-trip.
// ---------------------------------------------------------------------------
#define QSTR  40
#define FBK   32
#define FASTR 40                       // 80B rows (odd 16B multiple)
#define FBSTR 200                      // 400B rows (odd 16B multiple)
#define FA_BUF (64 * FASTR * 2)        // 5120 B
#define FB_BUF (FBK * FBSTR * 2)       // 12800 B
#define FSTAGES 4
#define FUSED_SMEM (FSTAGES * (FA_BUF + FB_BUF))   // 71680 B
// attn arrays aliased over stage buffers (used only after mainloop +sync):
#define AOFF_QS 0
#define AOFF_KS 10240
#define AOFF_VS 20480

__global__ __launch_bounds__(256) void fused_qkv_attn_kernel(
    const __half* __restrict__ xh, const __half* __restrict__ wqkv,
    const float* __restrict__ qkv_b, const float* __restrict__ comb,
    __half* __restrict__ out)
{
    extern __shared__ char smraw[];
    __half* AsH = (__half*)smraw;
    __half* BsH = (__half*)(smraw + FSTAGES * FA_BUF);
    __half (*qs)[64][QSTR] = (__half(*)[64][QSTR])(smraw + AOFF_QS);
    __half (*ks)[64][QSTR] = (__half(*)[64][QSTR])(smraw + AOFF_KS);
    __half (*vs)[64][QSTR] = (__half(*)[64][QSTR])(smraw + AOFF_VS);

    const int hp = blockIdx.x;    // head pair 0..3
    const int b  = blockIdx.y;    // 0..2047

    const int tid  = threadIdx.x;
    const int lane = tid & 31;
    const int wid  = tid >> 5;
    const int g    = lane >> 2;
    const int t    = lane & 3;

    // GEMM-phase warp mapping: m-tile (wid&3), n-group (wid>>2) of 96 cols
    const int mt = wid & 3;
    const int ng = wid >> 2;

    // ---- loaders
    const __half* Abase = xh + (size_t)b * NSEQ * CDIM;
    const int a_r  = tid >> 2;                   // 0..63
    const int a_c  = (tid & 3) * 8;
    const int a_rc = (a_r < NSEQ) ? a_r : NSEQ - 1;   // clamp pad rows

    // B chunks: 32 rows x 24 chunks (192 halves) = 768 chunks, 3/thread
    int b_r[3], b_c8[3], b_gcol[3];
#pragma unroll
    for (int i = 0; i < 3; i++) {
        int q = i * 256 + tid;
        b_r[i]  = q / 24;
        b_c8[i] = (q - b_r[i] * 24) * 8;
        int m3  = b_c8[i] >> 6;
        b_gcol[i] = m3 * 256 + hp * 64 + (b_c8[i] & 63);
    }

    const unsigned asBase = (unsigned)__cvta_generic_to_shared(AsH);
    const unsigned bsBase = (unsigned)__cvta_generic_to_shared(BsH);
    const unsigned aOff = (unsigned)(a_r * FASTR + a_c) * 2;
    unsigned bOff[3];
#pragma unroll
    for (int i = 0; i < 3; i++)
        bOff[i] = (unsigned)(b_r[i] * FBSTR + b_c8[i]) * 2;

    const unsigned aFragBase = (unsigned)__cvta_generic_to_shared(
        &AsH[(mt * 16 + (lane & 15)) * FASTR + ((lane >> 4) << 3)]);
    const unsigned bFragBase = (unsigned)__cvta_generic_to_shared(
        &BsH[(lane & 15) * FBSTR + ng * 96 + ((lane >> 4) << 3)]);

    float acc[12][4];
#pragma unroll
    for (int nt = 0; nt < 12; nt++)
#pragma unroll
        for (int r = 0; r < 4; r++) acc[nt][r] = 0.f;

    // ---- prologue
#pragma unroll
    for (int s = 0; s < FSTAGES - 1; s++) {
        const int k0 = s * FBK;
        cp_async16(asBase + s * FA_BUF + aOff, Abase + (size_t)a_rc * CDIM + k0 + a_c);
#pragma unroll
        for (int i = 0; i < 3; i++)
            cp_async16(bsBase + s * FB_BUF + bOff[i],
                       wqkv + (size_t)(k0 + b_r[i]) * THREECD + b_gcol[i]);
        cp_commit();
    }
    asm volatile("cp.async.wait_group %0;" :: "n"(FSTAGES - 2));
    __syncthreads();

    // ---- mainloop: 8 k-iters
    int buf = 0;
    for (int kt = 0; kt < 8; kt++) {
        if (kt + FSTAGES - 1 < 8) {
            const int k0 = (kt + FSTAGES - 1) * FBK;
            const unsigned sb = (unsigned)((kt + FSTAGES - 1) & (FSTAGES - 1));
            cp_async16(asBase + sb * FA_BUF + aOff,
                       Abase + (size_t)a_rc * CDIM + k0 + a_c);
#pragma unroll
            for (int i = 0; i < 3; i++)
                cp_async16(bsBase + sb * FB_BUF + bOff[i],
                           wqkv + (size_t)(k0 + b_r[i]) * THREECD + b_gcol[i]);
        }
        cp_commit();

#pragma unroll
        for (int kc = 0; kc < 2; kc++) {
            unsigned af[4], bf[6][4];
            ldsm4(af, aFragBase + buf * FA_BUF + kc * 32);
#pragma unroll
            for (int db = 0; db < 6; db++)
                ldsm4t(bf[db], bFragBase + buf * FB_BUF + kc * (16 * FBSTR * 2) + db * 32);
#pragma unroll
            for (int nt = 0; nt < 12; nt++) {
                const unsigned b0 = bf[nt >> 1][(nt & 1) * 2];
                const unsigned b1 = bf[nt >> 1][(nt & 1) * 2 + 1];
                mma_f16(acc[nt], af, b0, b1);
            }
        }

        asm volatile("cp.async.wait_group %0;" :: "n"(FSTAGES - 2));
        __syncthreads();
        buf = (buf + 1) & (FSTAGES - 1);
    }
    __syncthreads();   // all frag reads done before aliased attn arrays written

    // ---- epilogue: bias + fp16 into smem q/k/v (same conversion as before)
    {
        const int er0 = mt * 16 + g, er1 = er0 + 8;
#pragma unroll
        for (int nt = 0; nt < 12; nt++) {
            const int c  = ng * 96 + nt * 8 + 2 * t;
            const int m3 = c >> 6, cw = c & 63;
            const int h2 = cw >> 5, cc = cw & 31;
            const float bb0 = qkv_b[m3 * 256 + hp * 64 + cw];
            const float bb1 = qkv_b[m3 * 256 + hp * 64 + cw + 1];
            __half2 hlo = __floats2half2_rn(acc[nt][0] + bb0, acc[nt][1] + bb1);
            __half2 hhi = __floats2half2_rn(acc[nt][2] + bb0, acc[nt][3] + bb1);
            __half (*dst)[64][QSTR] = (m3 == 0) ? qs : (m3 == 1) ? ks : vs;
            *(__half2*)&dst[h2][er0][cc] = hlo;
            *(__half2*)&dst[h2][er1][cc] = hhi;
        }
    }
    __syncthreads();

    // =======================================================================
    // Attention phase (round-16, register-resident P)
    // =======================================================================
    const int hh  = wid >> 2;
    const int row = (wid & 3) * 16;
    const int r0 = row + g, r1 = r0 + 8;
    const int h = hp * 2 + hh;
    const float scale = 0.17677669529663687f;
    const float* cb = comb + ((size_t)(b & (NW - 1)) * NHEADS + h) * NSEQ * NSEQ;

    float cA[14], cB[14];
#pragma unroll
    for (int nt = 0; nt < 7; nt++) {
#pragma unroll
        for (int cx = 0; cx < 2; cx++) {
            const int cc = nt * 8 + 2 * t + cx;
            cA[nt * 2 + cx] = (r0 < NSEQ && cc < NSEQ) ? cb[r0 * NSEQ + cc] : 0.f;
            cB[nt * 2 + cx] = (r1 < NSEQ && cc < NSEQ) ? cb[r1 * NSEQ + cc] : 0.f;
        }
    }

    float c_sc[7][4];
#pragma unroll
    for (int nt = 0; nt < 7; nt++)
#pragma unroll
        for (int r = 0; r < 4; r++) c_sc[nt][r] = 0.f;

    const unsigned qAddr = (unsigned)__cvta_generic_to_shared(
        &qs[hh][row + (lane & 15)][(lane >> 4) << 3]);
    const unsigned kAddr = (unsigned)__cvta_generic_to_shared(
        &ks[hh][(lane & 7) + ((lane >> 4) << 3)][((lane >> 3) & 1) << 3]);

#pragma unroll
    for (int kc = 0; kc < 2; kc++) {
        const int k0 = kc * 16;
        unsigned a[4];
        ldsm4(a, qAddr + k0 * 2);
        unsigned bf[4][4];
#pragma unroll
        for (int jb = 0; jb < 4; jb++)
            ldsm4(bf[jb], kAddr + (jb * 16 * QSTR + k0) * 2);
#pragma unroll
        for (int nt = 0; nt < 7; nt++) {
            const unsigned b0 = bf[nt >> 1][(nt & 1) * 2];
            const unsigned b1 = bf[nt >> 1][(nt & 1) * 2 + 1];
            mma_f16(c_sc[nt], a, b0, b1);
        }
    }

    float mx0 = -1e30f, mx1 = -1e30f;
#pragma unroll
    for (int nt = 0; nt < 7; nt++) {
#pragma unroll
        for (int cx = 0; cx < 2; cx++) {
            const int cc = nt * 8 + 2 * t + cx;
            float v0 = (r0 < NSEQ && cc < NSEQ)
                     ? fmaf(c_sc[nt][cx], scale, cA[nt * 2 + cx]) : -1e30f;
            float v1 = (r1 < NSEQ && cc < NSEQ)
                     ? fmaf(c_sc[nt][2 + cx], scale, cB[nt * 2 + cx]) : -1e30f;
            c_sc[nt][cx] = v0;     mx0 = fmaxf(mx0, v0);
            c_sc[nt][2 + cx] = v1; mx1 = fmaxf(mx1, v1);
        }
    }
    mx0 = fmaxf(mx0, __shfl_xor_sync(0xffffffffu, mx0, 1));
    mx0 = fmaxf(mx0, __shfl_xor_sync(0xffffffffu, mx0, 2));
    mx1 = fmaxf(mx1, __shfl_xor_sync(0xffffffffu, mx1, 1));
    mx1 = fmaxf(mx1, __shfl_xor_sync(0xffffffffu, mx1, 2));

    float s0 = 0.f, s1 = 0.f;
#pragma unroll
    for (int nt = 0; nt < 7; nt++) {
#pragma unroll
        for (int cx = 0; cx < 2; cx++) {
            float e0 = __expf(c_sc[nt][cx] - mx0);
            float e1 = __expf(c_sc[nt][2 + cx] - mx1);
            c_sc[nt][cx] = e0;     s0 += e0;
            c_sc[nt][2 + cx] = e1; s1 += e1;
        }
    }
    s0 += __shfl_xor_sync(0xffffffffu, s0, 1);
    s0 += __shfl_xor_sync(0xffffffffu, s0, 2);
    s1 += __shfl_xor_sync(0xffffffffu, s1, 1);
    s1 += __shfl_xor_sync(0xffffffffu, s1, 2);
    const float inv0 = 1.f / s0, inv1 = 1.f / s1;

    unsigned ph0[7], ph1[7];
#pragma unroll
    for (int nt = 0; nt < 7; nt++) {
        const int cc = nt * 8 + 2 * t;
        float p00 = (cc     < NSEQ) ? c_sc[nt][0] * inv0 : 0.f;
        float p01 = (cc + 1 < NSEQ) ? c_sc[nt][1] * inv0 : 0.f;
        float p10 = (cc     < NSEQ) ? c_sc[nt][2] * inv1 : 0.f;
        float p11 = (cc + 1 < NSEQ) ? c_sc[nt][3] * inv1 : 0.f;
        __half2 h0 = __floats2half2_rn(p00, p01);
        __half2 h1 = __floats2half2_rn(p10, p11);
        ph0[nt] = *(unsigned*)&h0;
        ph1[nt] = *(unsigned*)&h1;
    }

    float c_o[4][4];
#pragma unroll
    for (int nt = 0; nt < 4; nt++)
#pragma unroll
        for (int r = 0; r < 4; r++) c_o[nt][r] = 0.f;

    const unsigned vAddr = (unsigned)__cvta_generic_to_shared(
        &vs[hh][lane & 15][(lane >> 4) << 3]);

#pragma unroll
    for (int kc = 0; kc < 4; kc++) {
        const int k0 = kc * 16;
        unsigned ap[4];
        ap[0] = ph0[2 * kc];
        ap[1] = ph1[2 * kc];
        ap[2] = (2 * kc + 1 < 7) ? ph0[2 * kc + 1] : 0u;
        ap[3] = (2 * kc + 1 < 7) ? ph1[2 * kc + 1] : 0u;
        unsigned bf[2][4];
#pragma unroll
        for (int db = 0; db < 2; db++)
            ldsm4t(bf[db], vAddr + (k0 * QSTR + db * 16) * 2);
#pragma unroll
        for (int nt = 0; nt < 4; nt++) {
            const unsigned b0 = bf[nt >> 1][(nt & 1) * 2];
            const unsigned b1 = bf[nt >> 1][(nt & 1) * 2 + 1];
            mma_f16(c_o[nt], ap, b0, b1);
        }
    }

    __half* obase = out + (size_t)b * NSEQ * CDIM + h * DHEAD;
#pragma unroll
    for (int nt = 0; nt < 4; nt++) {
        const int dd = nt * 8 + 2 * t;
        if (r0 < NSEQ)
            *(__half2*)&obase[(size_t)r0 * CDIM + dd] =
                __floats2half2_rn(c_o[nt][0], c_o[nt][1]);
        if (r1 < NSEQ)
            *(__half2*)&obase[(size_t)r1 * CDIM + dd] =
                __floats2half2_rn(c_o[nt][2], c_o[nt][3]);
    }
}

// ---------------------------------------------------------------------------
extern "C" void kernel_launch(void* const* d_in, const int* in_sizes, int n_in,
                              void* d_out, int out_size)
{
    const float* x          = (const float*)d_in[0];
    const float* mask       = (const float*)d_in[1];
    const float* qkv_w      = (const float*)d_in[2];
    const float* qkv_b      = (const float*)d_in[3];
    const float* proj_w     = (const float*)d_in[4];
    const float* proj_b     = (const float*)d_in[5];
    const float* bias_table = (const float*)d_in[6];
    float* out = (float*)d_out;

    __half *xh, *wqkvh, *wprojh, *aoh;
    float *comb_ptr;
    cudaGetSymbolAddress((void**)&xh, g_xh);
    cudaGetSymbolAddress((void**)&wqkvh, g_wqkvh);
    cudaGetSymbolAddress((void**)&wprojh, g_wprojh);
    cudaGetSymbolAddress((void**)&aoh, g_aoh);
    cudaGetSymbolAddress((void**)&comb_ptr, g_comb);

    static bool attr_set = false;
    if (!attr_set) {
        cudaFuncSetAttribute(gemm_f16_kernel,
                             cudaFuncAttributeMaxDynamicSharedMemorySize, GEMM_SMEM);
        cudaFuncSetAttribute(fused_qkv_attn_kernel,
                             cudaFuncAttributeMaxDynamicSharedMemorySize, FUSED_SMEM);
        attr_set = true;
    }

    const int M = B_TOT * NSEQ;  // 100352

    // 0) fused prepass
    prepass_kernel<<<NB_TOTAL, 256>>>(
        (const float4*)x, (uint2*)xh,
        (const float4*)qkv_w, (uint2*)wqkvh,
        (const float4*)proj_w, (uint2*)wprojh,
        mask, bias_table, comb_ptr);
    // 1+2) fused qkv-GEMM + attention -> fp16 (no qkv round-trip)
    {
        dim3 grid(NHEADS / 2, B_TOT);
        fused_qkv_attn_kernel<<<grid, 256, FUSED_SMEM>>>(
            xh, wqkvh, qkv_b, comb_ptr, aoh);
    }
    // 3) out = attnout @ proj_w + proj_b -> fp32
    {
        dim3 grid(CDIM / GBN, M / GBM);
        gemm_f16_kernel<<<grid, 256, GEMM_SMEM>>>(aoh, wprojh, proj_b, out,
                                                  M, CDIM, CDIM);
    }
}